// round 2
// baseline (speedup 1.0000x reference)
#include <cuda_runtime.h>
#include <cuda_bf16.h>
#include <math.h>

// Problem constants
#define B_ 2
#define T_ 4096
#define C_ 2048
#define H_ 16
#define D_ 128
#define W_ 1024
#define M_ (B_*T_)          // 8192 rows
#define SCALE_ (0.08838834764831845f)   // 1/sqrt(128)

// ---------------- scratch (device globals; no cudaMalloc allowed) ----------
__device__ float g_q[(size_t)M_ * C_];
__device__ float g_k[(size_t)M_ * C_];
__device__ float g_v[(size_t)M_ * C_];
__device__ float g_o[(size_t)M_ * C_];

// ---------------- SGEMM: C = A[MxK] * B[KxN], row-major, fp32 --------------
#define BM 128
#define BN 128
#define BK 8
#define TM 8
#define TN 8

__global__ __launch_bounds__(256) void sgemm_kernel(
    const float* __restrict__ A, const float* __restrict__ Bm,
    float* __restrict__ Cm, int M, int N, int K)
{
    __shared__ float As[BK][BM];
    __shared__ float Bs[BK][BN];
    const int tid = threadIdx.x;
    const int bx = blockIdx.x;   // N tile
    const int by = blockIdx.y;   // M tile

    const float* Ab = A + (size_t)by * BM * K;
    const float* Bb = Bm + (size_t)bx * BN;

    const int rowA = tid >> 1;            // 0..127
    const int colA = (tid & 1) * 4;       // 0 or 4
    const int rowB = tid >> 5;            // 0..7
    const int colB = (tid & 31) * 4;      // 0..124

    const int tx = tid & 15;              // 0..15 (N dir)
    const int ty = tid >> 4;              // 0..15 (M dir)

    float acc[TM][TN];
#pragma unroll
    for (int i = 0; i < TM; i++)
#pragma unroll
        for (int j = 0; j < TN; j++) acc[i][j] = 0.f;

    for (int k0 = 0; k0 < K; k0 += BK) {
        float4 a4 = *(const float4*)(Ab + (size_t)rowA * K + k0 + colA);
        As[colA + 0][rowA] = a4.x;
        As[colA + 1][rowA] = a4.y;
        As[colA + 2][rowA] = a4.z;
        As[colA + 3][rowA] = a4.w;
        float4 b4 = *(const float4*)(Bb + (size_t)(k0 + rowB) * N + colB);
        *(float4*)(&Bs[rowB][colB]) = b4;
        __syncthreads();

#pragma unroll
        for (int kk = 0; kk < BK; kk++) {
            float a[TM], b[TN];
            float4 t0 = *(const float4*)(&As[kk][ty * TM]);
            float4 t1 = *(const float4*)(&As[kk][ty * TM + 4]);
            a[0]=t0.x; a[1]=t0.y; a[2]=t0.z; a[3]=t0.w;
            a[4]=t1.x; a[5]=t1.y; a[6]=t1.z; a[7]=t1.w;
            float4 u0 = *(const float4*)(&Bs[kk][tx * TN]);
            float4 u1 = *(const float4*)(&Bs[kk][tx * TN + 4]);
            b[0]=u0.x; b[1]=u0.y; b[2]=u0.z; b[3]=u0.w;
            b[4]=u1.x; b[5]=u1.y; b[6]=u1.z; b[7]=u1.w;
#pragma unroll
            for (int i = 0; i < TM; i++)
#pragma unroll
                for (int j = 0; j < TN; j++)
                    acc[i][j] += a[i] * b[j];
        }
        __syncthreads();
    }

    float* Cb = Cm + (size_t)(by * BM + ty * TM) * N + bx * BN + tx * TN;
#pragma unroll
    for (int i = 0; i < TM; i++) {
        float4 v0 = make_float4(acc[i][0], acc[i][1], acc[i][2], acc[i][3]);
        float4 v1 = make_float4(acc[i][4], acc[i][5], acc[i][6], acc[i][7]);
        *(float4*)(Cb + (size_t)i * N + 0) = v0;
        *(float4*)(Cb + (size_t)i * N + 4) = v1;
    }
}

// ---------------- gate: v += 2*sigmoid(x[:, :32] @ Wg)[h] * ve -------------
__global__ __launch_bounds__(256) void gate_kernel(
    const float* __restrict__ x, const float* __restrict__ ve,
    const float* __restrict__ Wg, float* __restrict__ v)
{
    const int m = blockIdx.x;
    const int tid = threadIdx.x;
    __shared__ float xg[32];
    __shared__ float g[H_];

    if (tid < 32) xg[tid] = x[(size_t)m * C_ + tid];
    __syncthreads();
    if (tid < H_) {
        float s = 0.f;
#pragma unroll
        for (int i = 0; i < 32; i++) s += xg[i] * Wg[i * H_ + tid];
        g[tid] = 2.f / (1.f + __expf(-s));
    }
    __syncthreads();

    const size_t base = (size_t)m * C_;
    for (int c = tid; c < C_; c += 256) {
        v[base + c] += g[c >> 7] * ve[base + c];
    }
}

// ---------------- RoPE + RMSNorm for q and k (warp per row,head) -----------
__global__ __launch_bounds__(256) void rope_rms_kernel(
    const float* __restrict__ cosT, const float* __restrict__ sinT,
    float* __restrict__ q, float* __restrict__ k)
{
    const int gw = (blockIdx.x * blockDim.x + threadIdx.x) >> 5;
    const int lane = threadIdx.x & 31;
    const int m = gw / H_;
    const int h = gw % H_;
    const int t = m % T_;

    const float c0 = cosT[t * 64 + lane];
    const float c1 = cosT[t * 64 + lane + 32];
    const float s0 = sinT[t * 64 + lane];
    const float s1 = sinT[t * 64 + lane + 32];

#pragma unroll
    for (int a = 0; a < 2; a++) {
        float* ptr = (a == 0 ? q : k) + (size_t)m * C_ + h * D_;
        float f0 = ptr[lane];
        float f1 = ptr[lane + 32];
        float f2 = ptr[lane + 64];
        float f3 = ptr[lane + 96];
        // rope: pairs (d, d+64) for d < 64
        float r0 =  f0 * c0 + f2 * s0;
        float r2 = -f0 * s0 + f2 * c0;
        float r1 =  f1 * c1 + f3 * s1;
        float r3 = -f1 * s1 + f3 * c1;
        float ss = r0*r0 + r1*r1 + r2*r2 + r3*r3;
#pragma unroll
        for (int off = 16; off; off >>= 1) ss += __shfl_xor_sync(0xffffffffu, ss, off);
        float sc = rsqrtf(ss * (1.f / 128.f) + 1e-6f);
        ptr[lane]      = r0 * sc;
        ptr[lane + 32] = r1 * sc;
        ptr[lane + 64] = r2 * sc;
        ptr[lane + 96] = r3 * sc;
    }
}

// ---------------- sliding-window attention (flash-style, fp32) -------------
// window: keys at global positions [max(0, t-W), t]
#define TQ 8
#define TK 32

__global__ __launch_bounds__(256) void attn_kernel(
    const float* __restrict__ Q, const float* __restrict__ K,
    const float* __restrict__ V, float* __restrict__ O)
{
    const int b = blockIdx.z;
    const int h = blockIdx.y;
    const int t0 = blockIdx.x * TQ;
    const int wid = threadIdx.x >> 5;
    const int lane = threadIdx.x & 31;
    const int tid = threadIdx.x;
    const int t = t0 + wid;

    __shared__ float Ks[TK][D_];
    __shared__ float Vs[TK][D_];

    const float* qrow = Q + ((size_t)(b * T_ + t)) * C_ + h * D_;
    const float q0 = qrow[lane];
    const float q1 = qrow[lane + 32];
    const float q2 = qrow[lane + 64];
    const float q3 = qrow[lane + 96];

    float mval = -1e30f, lsum = 0.f;
    float o0 = 0.f, o1 = 0.f, o2 = 0.f, o3 = 0.f;

    int lo = t0 - W_;
    if (lo < 0) lo = 0;
    lo &= ~(TK - 1);
    const int hi = t0 + TQ - 1;

    for (int ks = lo; ks <= hi; ks += TK) {
        // cooperative tile load: 32 keys x 128 dims, K and V
        for (int i = tid; i < TK * 32; i += 256) {
            int row = i >> 5;
            int col = (i & 31) << 2;
            size_t gidx = ((size_t)(b * T_ + ks + row)) * C_ + h * D_ + col;
            *(float4*)(&Ks[row][col]) = *(const float4*)(K + gidx);
            *(float4*)(&Vs[row][col]) = *(const float4*)(V + gidx);
        }
        __syncthreads();

#pragma unroll 4
        for (int j = 0; j < TK; j++) {
            int kt = ks + j;
            if (kt > t || kt < t - W_) continue;
            float s = q0 * Ks[j][lane] + q1 * Ks[j][lane + 32]
                    + q2 * Ks[j][lane + 64] + q3 * Ks[j][lane + 96];
#pragma unroll
            for (int off = 16; off; off >>= 1) s += __shfl_xor_sync(0xffffffffu, s, off);
            s *= SCALE_;
            float nm = fmaxf(mval, s);
            float corr = __expf(mval - nm);
            float p = __expf(s - nm);
            lsum = lsum * corr + p;
            o0 = o0 * corr + p * Vs[j][lane];
            o1 = o1 * corr + p * Vs[j][lane + 32];
            o2 = o2 * corr + p * Vs[j][lane + 64];
            o3 = o3 * corr + p * Vs[j][lane + 96];
            mval = nm;
        }
        __syncthreads();
    }

    const float inv = 1.f / lsum;
    float* orow = O + ((size_t)(b * T_ + t)) * C_ + h * D_;
    orow[lane]      = o0 * inv;
    orow[lane + 32] = o1 * inv;
    orow[lane + 64] = o2 * inv;
    orow[lane + 96] = o3 * inv;
}

// ---------------- launch ---------------------------------------------------
extern "C" void kernel_launch(void* const* d_in, const int* in_sizes, int n_in,
                              void* d_out, int out_size)
{
    const float* x     = (const float*)d_in[0];
    const float* ve    = (const float*)d_in[1];
    const float* cosT  = (const float*)d_in[2];
    const float* sinT  = (const float*)d_in[3];
    const float* Wq    = (const float*)d_in[4];
    const float* Wk    = (const float*)d_in[5];
    const float* Wv    = (const float*)d_in[6];
    const float* Wproj = (const float*)d_in[7];
    const float* Wg    = (const float*)d_in[8];
    // d_in[9] = window_size (1024, hardcoded as W_)
    float* out = (float*)d_out;

    float *q, *k, *v, *o;
    cudaGetSymbolAddress((void**)&q, g_q);
    cudaGetSymbolAddress((void**)&k, g_k);
    cudaGetSymbolAddress((void**)&v, g_v);
    cudaGetSymbolAddress((void**)&o, g_o);

    dim3 gemm_grid(C_ / BN, M_ / BM);
    // QKV projections
    sgemm_kernel<<<gemm_grid, 256>>>(x, Wq, q, M_, C_, C_);
    sgemm_kernel<<<gemm_grid, 256>>>(x, Wk, k, M_, C_, C_);
    sgemm_kernel<<<gemm_grid, 256>>>(x, Wv, v, M_, C_, C_);

    // gated value-embedding add
    gate_kernel<<<M_, 256>>>(x, ve, Wg, v);

    // RoPE + RMS on q, k
    rope_rms_kernel<<<(M_ * H_) / 8, 256>>>(cosT, sinT, q, k);

    // sliding-window attention
    dim3 attn_grid(T_ / TQ, H_, B_);
    attn_kernel<<<attn_grid, 256>>>(q, k, v, o);

    // output projection
    sgemm_kernel<<<gemm_grid, 256>>>(o, Wproj, out, M_, C_, C_);
}

// round 3
// speedup vs baseline: 1.4721x; 1.4721x over previous
#include <cuda_runtime.h>
#include <cuda_bf16.h>
#include <math.h>

// Problem constants
#define B_ 2
#define T_ 4096
#define C_ 2048
#define H_ 16
#define D_ 128
#define W_ 1024
#define M_ (B_*T_)          // 8192 rows
#define SCALE_ (0.08838834764831845f)   // 1/sqrt(128)

// ---------------- scratch (device globals; no cudaMalloc allowed) ----------
__device__ float g_q[(size_t)M_ * C_];
__device__ float g_k[(size_t)M_ * C_];
__device__ float g_v[(size_t)M_ * C_];
__device__ float g_o[(size_t)M_ * C_];

// ---------------- TF32 tensor-core GEMM: C = A[MxK] * B[KxN] ---------------
// 128x128 CTA tile, BK=32, 8 warps (2x4), each warp 64x32 (4x4 m16n8 tiles).
#define GBM 128
#define GBN 128
#define GBK 32

__device__ __forceinline__ unsigned f2tf(float f) {
    unsigned u;
    asm("cvt.rna.tf32.f32 %0, %1;" : "=r"(u) : "f"(f));
    return u;
}

__device__ __forceinline__ void mma_tf32(float* c, const unsigned* a, const unsigned* b) {
    asm volatile(
        "mma.sync.aligned.m16n8k8.row.col.f32.tf32.tf32.f32 "
        "{%0,%1,%2,%3}, {%4,%5,%6,%7}, {%8,%9}, {%0,%1,%2,%3};"
        : "+f"(c[0]), "+f"(c[1]), "+f"(c[2]), "+f"(c[3])
        : "r"(a[0]), "r"(a[1]), "r"(a[2]), "r"(a[3]), "r"(b[0]), "r"(b[1]));
}

__global__ __launch_bounds__(256) void tf32_gemm(
    const float* __restrict__ A, const float* __restrict__ Bm,
    float* __restrict__ Cm, int M, int N, int K)
{
    __shared__ float As[GBM][GBK + 4];   // pad 4 -> conflict-free frag loads
    __shared__ float Bs[GBK][GBN + 8];   // pad 8 -> conflict-free frag loads

    const int tid = threadIdx.x;
    const int bx = blockIdx.x;           // N tile
    const int by = blockIdx.y;           // M tile
    const int lane = tid & 31;
    const int wid = tid >> 5;
    const int wm = (wid & 1) * 64;       // warp row offset in tile
    const int wn = (wid >> 1) * 32;      // warp col offset in tile
    const int g = lane >> 2;             // group id 0..7
    const int tq = lane & 3;             // thread-in-group 0..3

    // global load mapping
    const int arow = tid >> 1;           // 0..127
    const int acol = (tid & 1) * 16;     // 0 or 16
    const int brow = tid >> 3;           // 0..31
    const int bcol = (tid & 7) * 16;     // 0..112

    const float* Ag = A + (size_t)(by * GBM + arow) * K + acol;
    const float* Bg = Bm + (size_t)brow * N + bx * GBN + bcol;

    float acc[4][4][4];
#pragma unroll
    for (int mt = 0; mt < 4; mt++)
#pragma unroll
        for (int nt = 0; nt < 4; nt++)
#pragma unroll
            for (int i = 0; i < 4; i++) acc[mt][nt][i] = 0.f;

    float4 ar[4], br[4];

    // prologue: load tile 0
#pragma unroll
    for (int i = 0; i < 4; i++) {
        ar[i] = *(const float4*)(Ag + i * 4);
        br[i] = *(const float4*)(Bg + i * 4);
    }
#pragma unroll
    for (int i = 0; i < 4; i++) {
        As[arow][acol + i*4 + 0] = __uint_as_float(f2tf(ar[i].x));
        As[arow][acol + i*4 + 1] = __uint_as_float(f2tf(ar[i].y));
        As[arow][acol + i*4 + 2] = __uint_as_float(f2tf(ar[i].z));
        As[arow][acol + i*4 + 3] = __uint_as_float(f2tf(ar[i].w));
        Bs[brow][bcol + i*4 + 0] = __uint_as_float(f2tf(br[i].x));
        Bs[brow][bcol + i*4 + 1] = __uint_as_float(f2tf(br[i].y));
        Bs[brow][bcol + i*4 + 2] = __uint_as_float(f2tf(br[i].z));
        Bs[brow][bcol + i*4 + 3] = __uint_as_float(f2tf(br[i].w));
    }
    __syncthreads();

    const int ntiles = K / GBK;
    for (int kt = 0; kt < ntiles; kt++) {
        const bool has_next = (kt + 1 < ntiles);
        if (has_next) {
            const float* Agn = Ag + (kt + 1) * GBK;
            const float* Bgn = Bg + (size_t)(kt + 1) * GBK * N;
#pragma unroll
            for (int i = 0; i < 4; i++) {
                ar[i] = *(const float4*)(Agn + i * 4);
                br[i] = *(const float4*)(Bgn + i * 4);
            }
        }

        // compute current tile from smem
#pragma unroll
        for (int ks = 0; ks < 4; ks++) {
            const int k = ks * 8 + tq;
            unsigned a[4][4], b[4][2];
#pragma unroll
            for (int mt = 0; mt < 4; mt++) {
                const int m = wm + mt * 16 + g;
                a[mt][0] = __float_as_uint(As[m][k]);
                a[mt][1] = __float_as_uint(As[m + 8][k]);
                a[mt][2] = __float_as_uint(As[m][k + 4]);
                a[mt][3] = __float_as_uint(As[m + 8][k + 4]);
            }
#pragma unroll
            for (int nt = 0; nt < 4; nt++) {
                const int n = wn + nt * 8 + g;
                b[nt][0] = __float_as_uint(Bs[k][n]);
                b[nt][1] = __float_as_uint(Bs[ks * 8 + tq + 4][n]);
            }
#pragma unroll
            for (int mt = 0; mt < 4; mt++)
#pragma unroll
                for (int nt = 0; nt < 4; nt++)
                    mma_tf32(acc[mt][nt], a[mt], b[nt]);
        }
        __syncthreads();

        if (has_next) {
#pragma unroll
            for (int i = 0; i < 4; i++) {
                As[arow][acol + i*4 + 0] = __uint_as_float(f2tf(ar[i].x));
                As[arow][acol + i*4 + 1] = __uint_as_float(f2tf(ar[i].y));
                As[arow][acol + i*4 + 2] = __uint_as_float(f2tf(ar[i].z));
                As[arow][acol + i*4 + 3] = __uint_as_float(f2tf(ar[i].w));
                Bs[brow][bcol + i*4 + 0] = __uint_as_float(f2tf(br[i].x));
                Bs[brow][bcol + i*4 + 1] = __uint_as_float(f2tf(br[i].y));
                Bs[brow][bcol + i*4 + 2] = __uint_as_float(f2tf(br[i].z));
                Bs[brow][bcol + i*4 + 3] = __uint_as_float(f2tf(br[i].w));
            }
        }
        __syncthreads();
    }

    // epilogue: write accumulators
#pragma unroll
    for (int mt = 0; mt < 4; mt++) {
        const int r0 = by * GBM + wm + mt * 16 + g;
#pragma unroll
        for (int nt = 0; nt < 4; nt++) {
            const int c0 = bx * GBN + wn + nt * 8 + 2 * tq;
            *(float2*)(Cm + (size_t)r0 * N + c0) = make_float2(acc[mt][nt][0], acc[mt][nt][1]);
            *(float2*)(Cm + (size_t)(r0 + 8) * N + c0) = make_float2(acc[mt][nt][2], acc[mt][nt][3]);
        }
    }
}

// ---------------- gate: v += 2*sigmoid(x[:, :32] @ Wg)[h] * ve -------------
__global__ __launch_bounds__(256) void gate_kernel(
    const float* __restrict__ x, const float* __restrict__ ve,
    const float* __restrict__ Wg, float* __restrict__ v)
{
    const int m = blockIdx.x;
    const int tid = threadIdx.x;
    __shared__ float xg[32];
    __shared__ float g[H_];

    if (tid < 32) xg[tid] = x[(size_t)m * C_ + tid];
    __syncthreads();
    if (tid < H_) {
        float s = 0.f;
#pragma unroll
        for (int i = 0; i < 32; i++) s += xg[i] * Wg[i * H_ + tid];
        g[tid] = 2.f / (1.f + __expf(-s));
    }
    __syncthreads();

    const size_t base = (size_t)m * C_;
    for (int c = tid; c < C_; c += 256) {
        v[base + c] += g[c >> 7] * ve[base + c];
    }
}

// ---------------- RoPE + RMSNorm for q and k (warp per row,head) -----------
__global__ __launch_bounds__(256) void rope_rms_kernel(
    const float* __restrict__ cosT, const float* __restrict__ sinT,
    float* __restrict__ q, float* __restrict__ k)
{
    const int gw = (blockIdx.x * blockDim.x + threadIdx.x) >> 5;
    const int lane = threadIdx.x & 31;
    const int m = gw / H_;
    const int h = gw % H_;
    const int t = m % T_;

    const float c0 = cosT[t * 64 + lane];
    const float c1 = cosT[t * 64 + lane + 32];
    const float s0 = sinT[t * 64 + lane];
    const float s1 = sinT[t * 64 + lane + 32];

#pragma unroll
    for (int a = 0; a < 2; a++) {
        float* ptr = (a == 0 ? q : k) + (size_t)m * C_ + h * D_;
        float f0 = ptr[lane];
        float f1 = ptr[lane + 32];
        float f2 = ptr[lane + 64];
        float f3 = ptr[lane + 96];
        float r0 =  f0 * c0 + f2 * s0;
        float r2 = -f0 * s0 + f2 * c0;
        float r1 =  f1 * c1 + f3 * s1;
        float r3 = -f1 * s1 + f3 * c1;
        float ss = r0*r0 + r1*r1 + r2*r2 + r3*r3;
#pragma unroll
        for (int off = 16; off; off >>= 1) ss += __shfl_xor_sync(0xffffffffu, ss, off);
        float sc = rsqrtf(ss * (1.f / 128.f) + 1e-6f);
        ptr[lane]      = r0 * sc;
        ptr[lane + 32] = r1 * sc;
        ptr[lane + 64] = r2 * sc;
        ptr[lane + 96] = r3 * sc;
    }
}

// ---------------- sliding-window attention (flash-style, fp32) -------------
#define TQ 8
#define TK 32

__global__ __launch_bounds__(256) void attn_kernel(
    const float* __restrict__ Q, const float* __restrict__ K,
    const float* __restrict__ V, float* __restrict__ O)
{
    const int b = blockIdx.z;
    const int h = blockIdx.y;
    const int t0 = blockIdx.x * TQ;
    const int wid = threadIdx.x >> 5;
    const int lane = threadIdx.x & 31;
    const int tid = threadIdx.x;
    const int t = t0 + wid;

    __shared__ float Ks[TK][D_];
    __shared__ float Vs[TK][D_];

    const float* qrow = Q + ((size_t)(b * T_ + t)) * C_ + h * D_;
    const float q0 = qrow[lane];
    const float q1 = qrow[lane + 32];
    const float q2 = qrow[lane + 64];
    const float q3 = qrow[lane + 96];

    float mval = -1e30f, lsum = 0.f;
    float o0 = 0.f, o1 = 0.f, o2 = 0.f, o3 = 0.f;

    int lo = t0 - W_;
    if (lo < 0) lo = 0;
    lo &= ~(TK - 1);
    const int hi = t0 + TQ - 1;

    for (int ks = lo; ks <= hi; ks += TK) {
        for (int i = tid; i < TK * 32; i += 256) {
            int row = i >> 5;
            int col = (i & 31) << 2;
            size_t gidx = ((size_t)(b * T_ + ks + row)) * C_ + h * D_ + col;
            *(float4*)(&Ks[row][col]) = *(const float4*)(K + gidx);
            *(float4*)(&Vs[row][col]) = *(const float4*)(V + gidx);
        }
        __syncthreads();

#pragma unroll 4
        for (int j = 0; j < TK; j++) {
            int kt = ks + j;
            if (kt > t || kt < t - W_) continue;
            float s = q0 * Ks[j][lane] + q1 * Ks[j][lane + 32]
                    + q2 * Ks[j][lane + 64] + q3 * Ks[j][lane + 96];
#pragma unroll
            for (int off = 16; off; off >>= 1) s += __shfl_xor_sync(0xffffffffu, s, off);
            s *= SCALE_;
            // one exp per key: branch is warp-uniform (s, mval uniform)
            if (s <= mval) {
                float p = __expf(s - mval);
                lsum += p;
                o0 += p * Vs[j][lane];
                o1 += p * Vs[j][lane + 32];
                o2 += p * Vs[j][lane + 64];
                o3 += p * Vs[j][lane + 96];
            } else {
                float corr = __expf(mval - s);
                mval = s;
                lsum = lsum * corr + 1.f;
                o0 = o0 * corr + Vs[j][lane];
                o1 = o1 * corr + Vs[j][lane + 32];
                o2 = o2 * corr + Vs[j][lane + 64];
                o3 = o3 * corr + Vs[j][lane + 96];
            }
        }
        __syncthreads();
    }

    const float inv = 1.f / lsum;
    float* orow = O + ((size_t)(b * T_ + t)) * C_ + h * D_;
    orow[lane]      = o0 * inv;
    orow[lane + 32] = o1 * inv;
    orow[lane + 64] = o2 * inv;
    orow[lane + 96] = o3 * inv;
}

// ---------------- launch ---------------------------------------------------
extern "C" void kernel_launch(void* const* d_in, const int* in_sizes, int n_in,
                              void* d_out, int out_size)
{
    const float* x     = (const float*)d_in[0];
    const float* ve    = (const float*)d_in[1];
    const float* cosT  = (const float*)d_in[2];
    const float* sinT  = (const float*)d_in[3];
    const float* Wq    = (const float*)d_in[4];
    const float* Wk    = (const float*)d_in[5];
    const float* Wv    = (const float*)d_in[6];
    const float* Wproj = (const float*)d_in[7];
    const float* Wg    = (const float*)d_in[8];
    float* out = (float*)d_out;

    float *q, *k, *v, *o;
    cudaGetSymbolAddress((void**)&q, g_q);
    cudaGetSymbolAddress((void**)&k, g_k);
    cudaGetSymbolAddress((void**)&v, g_v);
    cudaGetSymbolAddress((void**)&o, g_o);

    dim3 gemm_grid(C_ / GBN, M_ / GBM);
    tf32_gemm<<<gemm_grid, 256>>>(x, Wq, q, M_, C_, C_);
    tf32_gemm<<<gemm_grid, 256>>>(x, Wk, k, M_, C_, C_);
    tf32_gemm<<<gemm_grid, 256>>>(x, Wv, v, M_, C_, C_);

    gate_kernel<<<M_, 256>>>(x, ve, Wg, v);
    rope_rms_kernel<<<(M_ * H_) / 8, 256>>>(cosT, sinT, q, k);

    dim3 attn_grid(T_ / TQ, H_, B_);
    attn_kernel<<<attn_grid, 256>>>(q, k, v, o);

    tf32_gemm<<<gemm_grid, 256>>>(o, Wproj, out, M_, C_, C_);
}

// round 4
// speedup vs baseline: 3.5781x; 2.4306x over previous
#include <cuda_runtime.h>
#include <cuda_bf16.h>
#include <math.h>

// Problem constants
#define B_ 2
#define T_ 4096
#define C_ 2048
#define H_ 16
#define D_ 128
#define W_ 1024
#define M_ (B_*T_)          // 8192 rows
#define SCALE_ (0.08838834764831845f)   // 1/sqrt(128)

// ---------------- scratch (device globals; no cudaMalloc allowed) ----------
__device__ float g_q[(size_t)M_ * C_];
__device__ float g_k[(size_t)M_ * C_];
__device__ float g_v[(size_t)M_ * C_];
__device__ float g_o[(size_t)M_ * C_];

// ---------------- common mma helpers ---------------------------------------
__device__ __forceinline__ unsigned f2tf(float f) {
    unsigned u;
    asm("cvt.rna.tf32.f32 %0, %1;" : "=r"(u) : "f"(f));
    return u;
}

__device__ __forceinline__ void mma_tf32(float* c, const unsigned* a, const unsigned* b) {
    asm volatile(
        "mma.sync.aligned.m16n8k8.row.col.f32.tf32.tf32.f32 "
        "{%0,%1,%2,%3}, {%4,%5,%6,%7}, {%8,%9}, {%0,%1,%2,%3};"
        : "+f"(c[0]), "+f"(c[1]), "+f"(c[2]), "+f"(c[3])
        : "r"(a[0]), "r"(a[1]), "r"(a[2]), "r"(a[3]), "r"(b[0]), "r"(b[1]));
}

// ---------------- TF32 tensor-core GEMM: C = A[MxK] * B[KxN] ---------------
#define GBM 128
#define GBN 128
#define GBK 32

__global__ __launch_bounds__(256) void tf32_gemm(
    const float* __restrict__ A, const float* __restrict__ Bm,
    float* __restrict__ Cm, int M, int N, int K)
{
    __shared__ float As[GBM][GBK + 4];
    __shared__ float Bs[GBK][GBN + 8];

    const int tid = threadIdx.x;
    const int bx = blockIdx.x;
    const int by = blockIdx.y;
    const int lane = tid & 31;
    const int wid = tid >> 5;
    const int wm = (wid & 1) * 64;
    const int wn = (wid >> 1) * 32;
    const int g = lane >> 2;
    const int tq = lane & 3;

    const int arow = tid >> 1;
    const int acol = (tid & 1) * 16;
    const int brow = tid >> 3;
    const int bcol = (tid & 7) * 16;

    const float* Ag = A + (size_t)(by * GBM + arow) * K + acol;
    const float* Bg = Bm + (size_t)brow * N + bx * GBN + bcol;

    float acc[4][4][4];
#pragma unroll
    for (int mt = 0; mt < 4; mt++)
#pragma unroll
        for (int nt = 0; nt < 4; nt++)
#pragma unroll
            for (int i = 0; i < 4; i++) acc[mt][nt][i] = 0.f;

    float4 ar[4], br[4];

#pragma unroll
    for (int i = 0; i < 4; i++) {
        ar[i] = *(const float4*)(Ag + i * 4);
        br[i] = *(const float4*)(Bg + i * 4);
    }
#pragma unroll
    for (int i = 0; i < 4; i++) {
        As[arow][acol + i*4 + 0] = __uint_as_float(f2tf(ar[i].x));
        As[arow][acol + i*4 + 1] = __uint_as_float(f2tf(ar[i].y));
        As[arow][acol + i*4 + 2] = __uint_as_float(f2tf(ar[i].z));
        As[arow][acol + i*4 + 3] = __uint_as_float(f2tf(ar[i].w));
        Bs[brow][bcol + i*4 + 0] = __uint_as_float(f2tf(br[i].x));
        Bs[brow][bcol + i*4 + 1] = __uint_as_float(f2tf(br[i].y));
        Bs[brow][bcol + i*4 + 2] = __uint_as_float(f2tf(br[i].z));
        Bs[brow][bcol + i*4 + 3] = __uint_as_float(f2tf(br[i].w));
    }
    __syncthreads();

    const int ntiles = K / GBK;
    for (int kt = 0; kt < ntiles; kt++) {
        const bool has_next = (kt + 1 < ntiles);
        if (has_next) {
            const float* Agn = Ag + (kt + 1) * GBK;
            const float* Bgn = Bg + (size_t)(kt + 1) * GBK * N;
#pragma unroll
            for (int i = 0; i < 4; i++) {
                ar[i] = *(const float4*)(Agn + i * 4);
                br[i] = *(const float4*)(Bgn + i * 4);
            }
        }

#pragma unroll
        for (int ks = 0; ks < 4; ks++) {
            const int k = ks * 8 + tq;
            unsigned a[4][4], b[4][2];
#pragma unroll
            for (int mt = 0; mt < 4; mt++) {
                const int m = wm + mt * 16 + g;
                a[mt][0] = __float_as_uint(As[m][k]);
                a[mt][1] = __float_as_uint(As[m + 8][k]);
                a[mt][2] = __float_as_uint(As[m][k + 4]);
                a[mt][3] = __float_as_uint(As[m + 8][k + 4]);
            }
#pragma unroll
            for (int nt = 0; nt < 4; nt++) {
                const int n = wn + nt * 8 + g;
                b[nt][0] = __float_as_uint(Bs[k][n]);
                b[nt][1] = __float_as_uint(Bs[k + 4][n]);
            }
#pragma unroll
            for (int mt = 0; mt < 4; mt++)
#pragma unroll
                for (int nt = 0; nt < 4; nt++)
                    mma_tf32(acc[mt][nt], a[mt], b[nt]);
        }
        __syncthreads();

        if (has_next) {
#pragma unroll
            for (int i = 0; i < 4; i++) {
                As[arow][acol + i*4 + 0] = __uint_as_float(f2tf(ar[i].x));
                As[arow][acol + i*4 + 1] = __uint_as_float(f2tf(ar[i].y));
                As[arow][acol + i*4 + 2] = __uint_as_float(f2tf(ar[i].z));
                As[arow][acol + i*4 + 3] = __uint_as_float(f2tf(ar[i].w));
                Bs[brow][bcol + i*4 + 0] = __uint_as_float(f2tf(br[i].x));
                Bs[brow][bcol + i*4 + 1] = __uint_as_float(f2tf(br[i].y));
                Bs[brow][bcol + i*4 + 2] = __uint_as_float(f2tf(br[i].z));
                Bs[brow][bcol + i*4 + 3] = __uint_as_float(f2tf(br[i].w));
            }
        }
        __syncthreads();
    }

#pragma unroll
    for (int mt = 0; mt < 4; mt++) {
        const int r0 = by * GBM + wm + mt * 16 + g;
#pragma unroll
        for (int nt = 0; nt < 4; nt++) {
            const int c0 = bx * GBN + wn + nt * 8 + 2 * tq;
            *(float2*)(Cm + (size_t)r0 * N + c0) = make_float2(acc[mt][nt][0], acc[mt][nt][1]);
            *(float2*)(Cm + (size_t)(r0 + 8) * N + c0) = make_float2(acc[mt][nt][2], acc[mt][nt][3]);
        }
    }
}

// ---------------- gate: v += 2*sigmoid(x[:, :32] @ Wg)[h] * ve -------------
__global__ __launch_bounds__(256) void gate_kernel(
    const float* __restrict__ x, const float* __restrict__ ve,
    const float* __restrict__ Wg, float* __restrict__ v)
{
    const int m = blockIdx.x;
    const int tid = threadIdx.x;
    __shared__ float xg[32];
    __shared__ float g[H_];

    if (tid < 32) xg[tid] = x[(size_t)m * C_ + tid];
    __syncthreads();
    if (tid < H_) {
        float s = 0.f;
#pragma unroll
        for (int i = 0; i < 32; i++) s += xg[i] * Wg[i * H_ + tid];
        g[tid] = 2.f / (1.f + __expf(-s));
    }
    __syncthreads();

    const size_t base = (size_t)m * C_;
    for (int c = tid; c < C_; c += 256) {
        v[base + c] += g[c >> 7] * ve[base + c];
    }
}

// ---------------- RoPE + RMSNorm for q and k (warp per row,head) -----------
__global__ __launch_bounds__(256) void rope_rms_kernel(
    const float* __restrict__ cosT, const float* __restrict__ sinT,
    float* __restrict__ q, float* __restrict__ k)
{
    const int gw = (blockIdx.x * blockDim.x + threadIdx.x) >> 5;
    const int lane = threadIdx.x & 31;
    const int m = gw / H_;
    const int h = gw % H_;
    const int t = m % T_;

    const float c0 = cosT[t * 64 + lane];
    const float c1 = cosT[t * 64 + lane + 32];
    const float s0 = sinT[t * 64 + lane];
    const float s1 = sinT[t * 64 + lane + 32];

#pragma unroll
    for (int a = 0; a < 2; a++) {
        float* ptr = (a == 0 ? q : k) + (size_t)m * C_ + h * D_;
        float f0 = ptr[lane];
        float f1 = ptr[lane + 32];
        float f2 = ptr[lane + 64];
        float f3 = ptr[lane + 96];
        float r0 =  f0 * c0 + f2 * s0;
        float r2 = -f0 * s0 + f2 * c0;
        float r1 =  f1 * c1 + f3 * s1;
        float r3 = -f1 * s1 + f3 * c1;
        float ss = r0*r0 + r1*r1 + r2*r2 + r3*r3;
#pragma unroll
        for (int off = 16; off; off >>= 1) ss += __shfl_xor_sync(0xffffffffu, ss, off);
        float sc = rsqrtf(ss * (1.f / 128.f) + 1e-6f);
        ptr[lane]      = r0 * sc;
        ptr[lane + 32] = r1 * sc;
        ptr[lane + 64] = r2 * sc;
        ptr[lane + 96] = r3 * sc;
    }
}

// ---------------- tensor-core sliding-window attention ---------------------
// CTA: 256 threads, 8 warps, 128 queries of one (b,h). Key tiles of 64.
#define AQ 128
#define ATK 64
#define KS_STRIDE 132   // 128+4, conflict-free S B-frag loads
#define VS_STRIDE 136   // 128+8, conflict-free PV B-frag loads
#define PS_STRIDE 68    // 64+4, conflict-free PV A-frag loads
#define SMEM_KS_OFF 0
#define SMEM_VS_OFF (ATK * KS_STRIDE)
#define SMEM_PS_OFF (SMEM_VS_OFF + ATK * VS_STRIDE)
#define SMEM_ATTN_FLOATS (SMEM_PS_OFF + AQ * PS_STRIDE)
#define SMEM_ATTN_BYTES (SMEM_ATTN_FLOATS * 4)

__global__ __launch_bounds__(256) void attn_mma_kernel(
    const float* __restrict__ Q, const float* __restrict__ K,
    const float* __restrict__ V, float* __restrict__ O)
{
    extern __shared__ float sm[];
    float* Ks = sm + SMEM_KS_OFF;
    float* Vs = sm + SMEM_VS_OFF;
    float* Ps = sm + SMEM_PS_OFF;

    const int b = blockIdx.z;
    const int h = blockIdx.y;
    const int t0 = blockIdx.x * AQ;
    const int tid = threadIdx.x;
    const int lane = tid & 31;
    const int wid = tid >> 5;        // 0..7
    const int g = lane >> 2;         // 0..7
    const int tq = lane & 3;         // 0..3
    const int wm = wid * 16;         // warp's query-row offset

    // ---- load Q fragments (persistent, scaled, tf32) ----
    unsigned qf[16][4];
    {
        const float* qb = Q + ((size_t)(b * T_ + t0 + wm)) * C_ + h * D_;
#pragma unroll
        for (int ks = 0; ks < 16; ks++) {
            const int c0 = ks * 8 + tq;
            qf[ks][0] = f2tf(qb[(size_t)g * C_ + c0] * SCALE_);
            qf[ks][1] = f2tf(qb[(size_t)(g + 8) * C_ + c0] * SCALE_);
            qf[ks][2] = f2tf(qb[(size_t)g * C_ + c0 + 4] * SCALE_);
            qf[ks][3] = f2tf(qb[(size_t)(g + 8) * C_ + c0 + 4] * SCALE_);
        }
    }

    float o[16][4];
#pragma unroll
    for (int nt = 0; nt < 16; nt++)
#pragma unroll
        for (int i = 0; i < 4; i++) o[nt][i] = 0.f;

    float m0 = -1e30f, m1 = -1e30f, l0 = 0.f, l1 = 0.f;
    const int trow0 = t0 + wm + g;
    const int trow1 = trow0 + 8;

    int lo = t0 - W_;
    if (lo < 0) lo = 0;

    for (int ks0 = lo; ks0 < t0 + AQ; ks0 += ATK) {
        // ---- cooperative K/V tile load (64 keys x 128 dims each) ----
#pragma unroll
        for (int it = 0; it < 8; it++) {
            const int idx = tid + it * 256;       // 0..2047 float4 slots
            const int row = idx >> 5;
            const int c4 = (idx & 31) * 4;
            const size_t gbase = ((size_t)(b * T_ + ks0 + row)) * C_ + h * D_ + c4;
            float4 kv = *(const float4*)(K + gbase);
            float4 vv = *(const float4*)(V + gbase);
            float* kd = Ks + row * KS_STRIDE + c4;
            kd[0] = __uint_as_float(f2tf(kv.x));
            kd[1] = __uint_as_float(f2tf(kv.y));
            kd[2] = __uint_as_float(f2tf(kv.z));
            kd[3] = __uint_as_float(f2tf(kv.w));
            float* vd = Vs + row * VS_STRIDE + c4;
            vd[0] = __uint_as_float(f2tf(vv.x));
            vd[1] = __uint_as_float(f2tf(vv.y));
            vd[2] = __uint_as_float(f2tf(vv.z));
            vd[3] = __uint_as_float(f2tf(vv.w));
        }
        __syncthreads();

        // ---- S = Q * K^T  (warp: 16 queries x 64 keys) ----
        float s[8][4];
#pragma unroll
        for (int nt = 0; nt < 8; nt++)
#pragma unroll
            for (int i = 0; i < 4; i++) s[nt][i] = 0.f;

#pragma unroll
        for (int ksp = 0; ksp < 16; ksp++) {
            const int k = ksp * 8 + tq;
            unsigned bfr[8][2];
#pragma unroll
            for (int nt = 0; nt < 8; nt++) {
                const int n = nt * 8 + g;
                bfr[nt][0] = __float_as_uint(Ks[n * KS_STRIDE + k]);
                bfr[nt][1] = __float_as_uint(Ks[n * KS_STRIDE + k + 4]);
            }
#pragma unroll
            for (int nt = 0; nt < 8; nt++)
                mma_tf32(s[nt], qf[ksp], bfr[nt]);
        }

        // ---- mask + online softmax ----
        float mt0 = -1e30f, mt1 = -1e30f;
#pragma unroll
        for (int nt = 0; nt < 8; nt++) {
            const int kt0 = ks0 + nt * 8 + 2 * tq;
            const int kt1 = kt0 + 1;
            s[nt][0] = (kt0 <= trow0 && kt0 >= trow0 - W_) ? s[nt][0] : -1e30f;
            s[nt][1] = (kt1 <= trow0 && kt1 >= trow0 - W_) ? s[nt][1] : -1e30f;
            s[nt][2] = (kt0 <= trow1 && kt0 >= trow1 - W_) ? s[nt][2] : -1e30f;
            s[nt][3] = (kt1 <= trow1 && kt1 >= trow1 - W_) ? s[nt][3] : -1e30f;
            mt0 = fmaxf(mt0, fmaxf(s[nt][0], s[nt][1]));
            mt1 = fmaxf(mt1, fmaxf(s[nt][2], s[nt][3]));
        }
        mt0 = fmaxf(mt0, __shfl_xor_sync(0xffffffffu, mt0, 1));
        mt0 = fmaxf(mt0, __shfl_xor_sync(0xffffffffu, mt0, 2));
        mt1 = fmaxf(mt1, __shfl_xor_sync(0xffffffffu, mt1, 1));
        mt1 = fmaxf(mt1, __shfl_xor_sync(0xffffffffu, mt1, 2));

        const float mn0 = fmaxf(m0, mt0);
        const float mn1 = fmaxf(m1, mt1);
        const float corr0 = __expf(m0 - mn0);
        const float corr1 = __expf(m1 - mn1);
        m0 = mn0; m1 = mn1;

        float ls0 = 0.f, ls1 = 0.f;
        float* pw0 = Ps + (wm + g) * PS_STRIDE;
        float* pw1 = Ps + (wm + g + 8) * PS_STRIDE;
#pragma unroll
        for (int nt = 0; nt < 8; nt++) {
            const int c = nt * 8 + 2 * tq;
            float p00 = (s[nt][0] > -1e29f) ? __expf(s[nt][0] - mn0) : 0.f;
            float p01 = (s[nt][1] > -1e29f) ? __expf(s[nt][1] - mn0) : 0.f;
            float p10 = (s[nt][2] > -1e29f) ? __expf(s[nt][2] - mn1) : 0.f;
            float p11 = (s[nt][3] > -1e29f) ? __expf(s[nt][3] - mn1) : 0.f;
            ls0 += p00 + p01;
            ls1 += p10 + p11;
            pw0[c]     = __uint_as_float(f2tf(p00));
            pw0[c + 1] = __uint_as_float(f2tf(p01));
            pw1[c]     = __uint_as_float(f2tf(p10));
            pw1[c + 1] = __uint_as_float(f2tf(p11));
        }
        ls0 += __shfl_xor_sync(0xffffffffu, ls0, 1);
        ls0 += __shfl_xor_sync(0xffffffffu, ls0, 2);
        ls1 += __shfl_xor_sync(0xffffffffu, ls1, 1);
        ls1 += __shfl_xor_sync(0xffffffffu, ls1, 2);
        l0 = l0 * corr0 + ls0;
        l1 = l1 * corr1 + ls1;

        // scale O accumulators
#pragma unroll
        for (int nt = 0; nt < 16; nt++) {
            o[nt][0] *= corr0; o[nt][1] *= corr0;
            o[nt][2] *= corr1; o[nt][3] *= corr1;
        }

        __syncwarp();   // Ps written by this warp only; make visible to itself

        // ---- O += P * V  (warp: 16 queries x 128 dims, k = 64 keys) ----
#pragma unroll
        for (int ksp = 0; ksp < 8; ksp++) {
            const int k = ksp * 8 + tq;
            unsigned a[4];
            a[0] = __float_as_uint(Ps[(wm + g) * PS_STRIDE + k]);
            a[1] = __float_as_uint(Ps[(wm + g + 8) * PS_STRIDE + k]);
            a[2] = __float_as_uint(Ps[(wm + g) * PS_STRIDE + k + 4]);
            a[3] = __float_as_uint(Ps[(wm + g + 8) * PS_STRIDE + k + 4]);
            unsigned bfr[2];
#pragma unroll
            for (int nt = 0; nt < 16; nt++) {
                const int n = nt * 8 + g;
                bfr[0] = __float_as_uint(Vs[k * VS_STRIDE + n]);
                bfr[1] = __float_as_uint(Vs[(k + 4) * VS_STRIDE + n]);
                mma_tf32(o[nt], a, bfr);
            }
        }
        __syncthreads();   // protect Ks/Vs before next tile load
    }

    // ---- epilogue ----
    const float inv0 = 1.f / l0;
    const float inv1 = 1.f / l1;
    float* ob0 = O + ((size_t)(b * T_ + trow0)) * C_ + h * D_;
    float* ob1 = O + ((size_t)(b * T_ + trow1)) * C_ + h * D_;
#pragma unroll
    for (int nt = 0; nt < 16; nt++) {
        const int c = nt * 8 + 2 * tq;
        *(float2*)(ob0 + c) = make_float2(o[nt][0] * inv0, o[nt][1] * inv0);
        *(float2*)(ob1 + c) = make_float2(o[nt][2] * inv1, o[nt][3] * inv1);
    }
}

// ---------------- launch ---------------------------------------------------
extern "C" void kernel_launch(void* const* d_in, const int* in_sizes, int n_in,
                              void* d_out, int out_size)
{
    const float* x     = (const float*)d_in[0];
    const float* ve    = (const float*)d_in[1];
    const float* cosT  = (const float*)d_in[2];
    const float* sinT  = (const float*)d_in[3];
    const float* Wq    = (const float*)d_in[4];
    const float* Wk    = (const float*)d_in[5];
    const float* Wv    = (const float*)d_in[6];
    const float* Wproj = (const float*)d_in[7];
    const float* Wg    = (const float*)d_in[8];
    float* out = (float*)d_out;

    float *q, *k, *v, *o;
    cudaGetSymbolAddress((void**)&q, g_q);
    cudaGetSymbolAddress((void**)&k, g_k);
    cudaGetSymbolAddress((void**)&v, g_v);
    cudaGetSymbolAddress((void**)&o, g_o);

    static int smem_set = 0;
    if (!smem_set) {
        cudaFuncSetAttribute(attn_mma_kernel,
                             cudaFuncAttributeMaxDynamicSharedMemorySize,
                             SMEM_ATTN_BYTES);
        smem_set = 1;
    }

    dim3 gemm_grid(C_ / GBN, M_ / GBM);
    tf32_gemm<<<gemm_grid, 256>>>(x, Wq, q, M_, C_, C_);
    tf32_gemm<<<gemm_grid, 256>>>(x, Wk, k, M_, C_, C_);
    tf32_gemm<<<gemm_grid, 256>>>(x, Wv, v, M_, C_, C_);

    gate_kernel<<<M_, 256>>>(x, ve, Wg, v);
    rope_rms_kernel<<<(M_ * H_) / 8, 256>>>(cosT, sinT, q, k);

    dim3 attn_grid(T_ / AQ, H_, B_);
    attn_mma_kernel<<<attn_grid, 256, SMEM_ATTN_BYTES>>>(q, k, v, o);

    tf32_gemm<<<gemm_grid, 256>>>(o, Wproj, out, M_, C_, C_);
}

// round 7
// speedup vs baseline: 5.9797x; 1.6712x over previous
#include <cuda_runtime.h>
#include <cuda_bf16.h>
#include <math.h>

// Problem constants
#define B_ 2
#define T_ 4096
#define C_ 2048
#define H_ 16
#define D_ 128
#define W_ 1024
#define M_ (B_*T_)          // 8192 rows
#define SCALE_ (0.08838834764831845f)   // 1/sqrt(128)

// ---------------- scratch (device globals; no cudaMalloc allowed) ----------
__device__ float g_q[(size_t)M_ * C_];
__device__ float g_k[(size_t)M_ * C_];
__device__ float g_v[(size_t)M_ * C_];
__device__ float g_o[(size_t)M_ * C_];
__device__ float g_xt[(size_t)M_ * C_];       // tf32-rounded x
__device__ float g_wq[(size_t)C_ * C_];
__device__ float g_wk[(size_t)C_ * C_];
__device__ float g_wv[(size_t)C_ * C_];
__device__ float g_wp[(size_t)C_ * C_];

// ---------------- common helpers -------------------------------------------
__device__ __forceinline__ unsigned f2tf(float f) {
    unsigned u;
    asm("cvt.rna.tf32.f32 %0, %1;" : "=r"(u) : "f"(f));
    return u;
}

__device__ __forceinline__ void mma_tf32(float* c, const unsigned* a, const unsigned* b) {
    asm volatile(
        "mma.sync.aligned.m16n8k8.row.col.f32.tf32.tf32.f32 "
        "{%0,%1,%2,%3}, {%4,%5,%6,%7}, {%8,%9}, {%0,%1,%2,%3};"
        : "+f"(c[0]), "+f"(c[1]), "+f"(c[2]), "+f"(c[3])
        : "r"(a[0]), "r"(a[1]), "r"(a[2]), "r"(a[3]), "r"(b[0]), "r"(b[1]));
}

__device__ __forceinline__ void cp16(unsigned s_addr, const float* g) {
    asm volatile("cp.async.cg.shared.global [%0], [%1], 16;\n" :: "r"(s_addr), "l"(g));
}

// ---------------- tf32 rounding pre-pass -----------------------------------
__global__ __launch_bounds__(256) void round_tf32_kernel(
    const float* __restrict__ in, float* __restrict__ out, int n4)
{
    int i = blockIdx.x * blockDim.x + threadIdx.x;
    if (i < n4) {
        float4 v = ((const float4*)in)[i];
        v.x = __uint_as_float(f2tf(v.x));
        v.y = __uint_as_float(f2tf(v.y));
        v.z = __uint_as_float(f2tf(v.z));
        v.w = __uint_as_float(f2tf(v.w));
        ((float4*)out)[i] = v;
    }
}

// ---------------- TF32 GEMM with cp.async 4-stage pipeline -----------------
// C = A[MxK] * B[KxN]; A,B pre-rounded to tf32 values in fp32 storage.
// 4 stages with prefetch depth 2: issue(kt+2) targets stage (kt+2)%4 whose
// last consumer was compute(kt-2); the per-iteration __syncthreads() already
// guarantees all threads finished compute(kt-2) -> no WAR race (the round-5
// 3-stage version raced on stage (kt-1)%3).
#define GBM 128
#define GBN 128
#define GBK 32
#define AS_STRIDE 36     // 128x36 floats
#define BS_STRIDE 136    // 32x136 floats
#define STAGE_FLOATS (GBM * AS_STRIDE + GBK * BS_STRIDE)   // 4608+4352 = 8960
#define GEMM_STAGES 4
#define GEMM_SMEM_BYTES (GEMM_STAGES * STAGE_FLOATS * 4)   // 143360

__global__ __launch_bounds__(256) void tf32_gemm_pipe(
    const float* __restrict__ A, const float* __restrict__ Bm,
    float* __restrict__ Cm, int M, int N, int K)
{
    extern __shared__ float sm[];
    const int tid = threadIdx.x;
    const int bx = blockIdx.x;
    const int by = blockIdx.y;
    const int lane = tid & 31;
    const int wid = tid >> 5;
    const int wm = (wid & 1) * 64;
    const int wn = (wid >> 1) * 32;
    const int g = lane >> 2;
    const int tq = lane & 3;

    const float* Abase = A + (size_t)by * GBM * K;
    const float* Bbase = Bm + bx * GBN;
    const unsigned sm_sa = (unsigned)__cvta_generic_to_shared(sm);

    float acc[4][4][4];
#pragma unroll
    for (int mt = 0; mt < 4; mt++)
#pragma unroll
        for (int nt = 0; nt < 4; nt++)
#pragma unroll
            for (int i = 0; i < 4; i++) acc[mt][nt][i] = 0.f;

    const int ntiles = K / GBK;

    auto issue = [&](int kt, int st) {
        const unsigned as0 = sm_sa + (unsigned)(st * STAGE_FLOATS) * 4u;
        const unsigned bs0 = as0 + GBM * AS_STRIDE * 4u;
#pragma unroll
        for (int i = 0; i < 4; i++) {
            const int cid = tid + i * 256;        // 0..1023
            const int r = cid >> 3;               // 0..127
            const int c = (cid & 7) * 4;          // 0..28
            cp16(as0 + (unsigned)(r * AS_STRIDE + c) * 4u,
                 Abase + (size_t)r * K + kt * GBK + c);
        }
#pragma unroll
        for (int i = 0; i < 4; i++) {
            const int cid = tid + i * 256;
            const int r = cid >> 5;               // 0..31
            const int c = (cid & 31) * 4;         // 0..124
            cp16(bs0 + (unsigned)(r * BS_STRIDE + c) * 4u,
                 Bbase + (size_t)(kt * GBK + r) * N + c);
        }
        asm volatile("cp.async.commit_group;\n");
    };

    issue(0, 0);
    issue(1, 1);

    for (int kt = 0; kt < ntiles; kt++) {
        if (kt + 2 < ntiles) issue(kt + 2, (kt + 2) % GEMM_STAGES);
        else asm volatile("cp.async.commit_group;\n");
        asm volatile("cp.async.wait_group 2;\n");
        __syncthreads();

        const float* As = sm + (kt % GEMM_STAGES) * STAGE_FLOATS;
        const float* Bs = As + GBM * AS_STRIDE;

#pragma unroll
        for (int ks = 0; ks < 4; ks++) {
            const int k = ks * 8 + tq;
            unsigned a[4][4], b[4][2];
#pragma unroll
            for (int mt = 0; mt < 4; mt++) {
                const int m = wm + mt * 16 + g;
                a[mt][0] = __float_as_uint(As[m * AS_STRIDE + k]);
                a[mt][1] = __float_as_uint(As[(m + 8) * AS_STRIDE + k]);
                a[mt][2] = __float_as_uint(As[m * AS_STRIDE + k + 4]);
                a[mt][3] = __float_as_uint(As[(m + 8) * AS_STRIDE + k + 4]);
            }
#pragma unroll
            for (int nt = 0; nt < 4; nt++) {
                const int n = wn + nt * 8 + g;
                b[nt][0] = __float_as_uint(Bs[k * BS_STRIDE + n]);
                b[nt][1] = __float_as_uint(Bs[(k + 4) * BS_STRIDE + n]);
            }
#pragma unroll
            for (int mt = 0; mt < 4; mt++)
#pragma unroll
                for (int nt = 0; nt < 4; nt++)
                    mma_tf32(acc[mt][nt], a[mt], b[nt]);
        }
    }

#pragma unroll
    for (int mt = 0; mt < 4; mt++) {
        const int r0 = by * GBM + wm + mt * 16 + g;
#pragma unroll
        for (int nt = 0; nt < 4; nt++) {
            const int c0 = bx * GBN + wn + nt * 8 + 2 * tq;
            *(float2*)(Cm + (size_t)r0 * N + c0) = make_float2(acc[mt][nt][0], acc[mt][nt][1]);
            *(float2*)(Cm + (size_t)(r0 + 8) * N + c0) = make_float2(acc[mt][nt][2], acc[mt][nt][3]);
        }
    }
}

// ---------------- gate: v += 2*sigmoid(x[:, :32] @ Wg)[h] * ve -------------
__global__ __launch_bounds__(256) void gate_kernel(
    const float* __restrict__ x, const float* __restrict__ ve,
    const float* __restrict__ Wg, float* __restrict__ v)
{
    const int m = blockIdx.x;
    const int tid = threadIdx.x;
    __shared__ float xg[32];
    __shared__ float g[H_];

    if (tid < 32) xg[tid] = x[(size_t)m * C_ + tid];
    __syncthreads();
    if (tid < H_) {
        float s = 0.f;
#pragma unroll
        for (int i = 0; i < 32; i++) s += xg[i] * Wg[i * H_ + tid];
        g[tid] = 2.f / (1.f + __expf(-s));
    }
    __syncthreads();

    const size_t base = (size_t)m * C_;
    for (int c = tid; c < C_; c += 256) {
        v[base + c] += g[c >> 7] * ve[base + c];
    }
}

// ---------------- RoPE + RMSNorm for q and k (warp per row,head) -----------
__global__ __launch_bounds__(256) void rope_rms_kernel(
    const float* __restrict__ cosT, const float* __restrict__ sinT,
    float* __restrict__ q, float* __restrict__ k)
{
    const int gw = (blockIdx.x * blockDim.x + threadIdx.x) >> 5;
    const int lane = threadIdx.x & 31;
    const int m = gw / H_;
    const int h = gw % H_;
    const int t = m % T_;

    const float c0 = cosT[t * 64 + lane];
    const float c1 = cosT[t * 64 + lane + 32];
    const float s0 = sinT[t * 64 + lane];
    const float s1 = sinT[t * 64 + lane + 32];

#pragma unroll
    for (int a = 0; a < 2; a++) {
        float* ptr = (a == 0 ? q : k) + (size_t)m * C_ + h * D_;
        float f0 = ptr[lane];
        float f1 = ptr[lane + 32];
        float f2 = ptr[lane + 64];
        float f3 = ptr[lane + 96];
        float r0 =  f0 * c0 + f2 * s0;
        float r2 = -f0 * s0 + f2 * c0;
        float r1 =  f1 * c1 + f3 * s1;
        float r3 = -f1 * s1 + f3 * c1;
        float ss = r0*r0 + r1*r1 + r2*r2 + r3*r3;
#pragma unroll
        for (int off = 16; off; off >>= 1) ss += __shfl_xor_sync(0xffffffffu, ss, off);
        float sc = rsqrtf(ss * (1.f / 128.f) + 1e-6f);
        ptr[lane]      = r0 * sc;
        ptr[lane + 32] = r1 * sc;
        ptr[lane + 64] = r2 * sc;
        ptr[lane + 96] = r3 * sc;
    }
}

// ---------------- tensor-core sliding-window attention ---------------------
#define AQ 128
#define ATK 64
#define KS_STRIDE 132
#define VS_STRIDE 136
#define PS_STRIDE 68
#define SMEM_KS_OFF 0
#define SMEM_VS_OFF (ATK * KS_STRIDE)
#define SMEM_PS_OFF (SMEM_VS_OFF + ATK * VS_STRIDE)
#define SMEM_ATTN_FLOATS (SMEM_PS_OFF + AQ * PS_STRIDE)
#define SMEM_ATTN_BYTES (SMEM_ATTN_FLOATS * 4)

__global__ __launch_bounds__(256) void attn_mma_kernel(
    const float* __restrict__ Q, const float* __restrict__ K,
    const float* __restrict__ V, float* __restrict__ O)
{
    extern __shared__ float sm[];
    float* Ks = sm + SMEM_KS_OFF;
    float* Vs = sm + SMEM_VS_OFF;
    float* Ps = sm + SMEM_PS_OFF;

    const int b = blockIdx.z;
    const int h = blockIdx.y;
    const int t0 = blockIdx.x * AQ;
    const int tid = threadIdx.x;
    const int lane = tid & 31;
    const int wid = tid >> 5;
    const int g = lane >> 2;
    const int tq = lane & 3;
    const int wm = wid * 16;

    unsigned qf[16][4];
    {
        const float* qb = Q + ((size_t)(b * T_ + t0 + wm)) * C_ + h * D_;
#pragma unroll
        for (int ks = 0; ks < 16; ks++) {
            const int c0 = ks * 8 + tq;
            qf[ks][0] = f2tf(qb[(size_t)g * C_ + c0] * SCALE_);
            qf[ks][1] = f2tf(qb[(size_t)(g + 8) * C_ + c0] * SCALE_);
            qf[ks][2] = f2tf(qb[(size_t)g * C_ + c0 + 4] * SCALE_);
            qf[ks][3] = f2tf(qb[(size_t)(g + 8) * C_ + c0 + 4] * SCALE_);
        }
    }

    float o[16][4];
#pragma unroll
    for (int nt = 0; nt < 16; nt++)
#pragma unroll
        for (int i = 0; i < 4; i++) o[nt][i] = 0.f;

    float m0 = -1e30f, m1 = -1e30f, l0 = 0.f, l1 = 0.f;
    const int trow0 = t0 + wm + g;
    const int trow1 = trow0 + 8;

    int lo = t0 - W_;
    if (lo < 0) lo = 0;

    for (int ks0 = lo; ks0 < t0 + AQ; ks0 += ATK) {
#pragma unroll
        for (int it = 0; it < 8; it++) {
            const int idx = tid + it * 256;
            const int row = idx >> 5;
            const int c4 = (idx & 31) * 4;
            const size_t gbase = ((size_t)(b * T_ + ks0 + row)) * C_ + h * D_ + c4;
            float4 kv = *(const float4*)(K + gbase);
            float4 vv = *(const float4*)(V + gbase);
            float* kd = Ks + row * KS_STRIDE + c4;
            kd[0] = __uint_as_float(f2tf(kv.x));
            kd[1] = __uint_as_float(f2tf(kv.y));
            kd[2] = __uint_as_float(f2tf(kv.z));
            kd[3] = __uint_as_float(f2tf(kv.w));
            float* vd = Vs + row * VS_STRIDE + c4;
            vd[0] = __uint_as_float(f2tf(vv.x));
            vd[1] = __uint_as_float(f2tf(vv.y));
            vd[2] = __uint_as_float(f2tf(vv.z));
            vd[3] = __uint_as_float(f2tf(vv.w));
        }
        __syncthreads();

        float s[8][4];
#pragma unroll
        for (int nt = 0; nt < 8; nt++)
#pragma unroll
            for (int i = 0; i < 4; i++) s[nt][i] = 0.f;

#pragma unroll
        for (int ksp = 0; ksp < 16; ksp++) {
            const int k = ksp * 8 + tq;
            unsigned bfr[8][2];
#pragma unroll
            for (int nt = 0; nt < 8; nt++) {
                const int n = nt * 8 + g;
                bfr[nt][0] = __float_as_uint(Ks[n * KS_STRIDE + k]);
                bfr[nt][1] = __float_as_uint(Ks[n * KS_STRIDE + k + 4]);
            }
#pragma unroll
            for (int nt = 0; nt < 8; nt++)
                mma_tf32(s[nt], qf[ksp], bfr[nt]);
        }

        float mt0 = -1e30f, mt1 = -1e30f;
#pragma unroll
        for (int nt = 0; nt < 8; nt++) {
            const int kt0 = ks0 + nt * 8 + 2 * tq;
            const int kt1 = kt0 + 1;
            s[nt][0] = (kt0 <= trow0 && kt0 >= trow0 - W_) ? s[nt][0] : -1e30f;
            s[nt][1] = (kt1 <= trow0 && kt1 >= trow0 - W_) ? s[nt][1] : -1e30f;
            s[nt][2] = (kt0 <= trow1 && kt0 >= trow1 - W_) ? s[nt][2] : -1e30f;
            s[nt][3] = (kt1 <= trow1 && kt1 >= trow1 - W_) ? s[nt][3] : -1e30f;
            mt0 = fmaxf(mt0, fmaxf(s[nt][0], s[nt][1]));
            mt1 = fmaxf(mt1, fmaxf(s[nt][2], s[nt][3]));
        }
        mt0 = fmaxf(mt0, __shfl_xor_sync(0xffffffffu, mt0, 1));
        mt0 = fmaxf(mt0, __shfl_xor_sync(0xffffffffu, mt0, 2));
        mt1 = fmaxf(mt1, __shfl_xor_sync(0xffffffffu, mt1, 1));
        mt1 = fmaxf(mt1, __shfl_xor_sync(0xffffffffu, mt1, 2));

        const float mn0 = fmaxf(m0, mt0);
        const float mn1 = fmaxf(m1, mt1);
        const float corr0 = __expf(m0 - mn0);
        const float corr1 = __expf(m1 - mn1);
        m0 = mn0; m1 = mn1;

        float ls0 = 0.f, ls1 = 0.f;
        float* pw0 = Ps + (wm + g) * PS_STRIDE;
        float* pw1 = Ps + (wm + g + 8) * PS_STRIDE;
#pragma unroll
        for (int nt = 0; nt < 8; nt++) {
            const int c = nt * 8 + 2 * tq;
            float p00 = (s[nt][0] > -1e29f) ? __expf(s[nt][0] - mn0) : 0.f;
            float p01 = (s[nt][1] > -1e29f) ? __expf(s[nt][1] - mn0) : 0.f;
            float p10 = (s[nt][2] > -1e29f) ? __expf(s[nt][2] - mn1) : 0.f;
            float p11 = (s[nt][3] > -1e29f) ? __expf(s[nt][3] - mn1) : 0.f;
            ls0 += p00 + p01;
            ls1 += p10 + p11;
            pw0[c]     = __uint_as_float(f2tf(p00));
            pw0[c + 1] = __uint_as_float(f2tf(p01));
            pw1[c]     = __uint_as_float(f2tf(p10));
            pw1[c + 1] = __uint_as_float(f2tf(p11));
        }
        ls0 += __shfl_xor_sync(0xffffffffu, ls0, 1);
        ls0 += __shfl_xor_sync(0xffffffffu, ls0, 2);
        ls1 += __shfl_xor_sync(0xffffffffu, ls1, 1);
        ls1 += __shfl_xor_sync(0xffffffffu, ls1, 2);
        l0 = l0 * corr0 + ls0;
        l1 = l1 * corr1 + ls1;

#pragma unroll
        for (int nt = 0; nt < 16; nt++) {
            o[nt][0] *= corr0; o[nt][1] *= corr0;
            o[nt][2] *= corr1; o[nt][3] *= corr1;
        }

        __syncwarp();

#pragma unroll
        for (int ksp = 0; ksp < 8; ksp++) {
            const int k = ksp * 8 + tq;
            unsigned a[4];
            a[0] = __float_as_uint(Ps[(wm + g) * PS_STRIDE + k]);
            a[1] = __float_as_uint(Ps[(wm + g + 8) * PS_STRIDE + k]);
            a[2] = __float_as_uint(Ps[(wm + g) * PS_STRIDE + k + 4]);
            a[3] = __float_as_uint(Ps[(wm + g + 8) * PS_STRIDE + k + 4]);
            unsigned bfr[2];
#pragma unroll
            for (int nt = 0; nt < 16; nt++) {
                const int n = nt * 8 + g;
                bfr[0] = __float_as_uint(Vs[k * VS_STRIDE + n]);
                bfr[1] = __float_as_uint(Vs[(k + 4) * VS_STRIDE + n]);
                mma_tf32(o[nt], a, bfr);
            }
        }
        __syncthreads();
    }

    // epilogue: write tf32-rounded output (proj GEMM reads it raw)
    const float inv0 = 1.f / l0;
    const float inv1 = 1.f / l1;
    float* ob0 = O + ((size_t)(b * T_ + trow0)) * C_ + h * D_;
    float* ob1 = O + ((size_t)(b * T_ + trow1)) * C_ + h * D_;
#pragma unroll
    for (int nt = 0; nt < 16; nt++) {
        const int c = nt * 8 + 2 * tq;
        *(float2*)(ob0 + c) = make_float2(__uint_as_float(f2tf(o[nt][0] * inv0)),
                                          __uint_as_float(f2tf(o[nt][1] * inv0)));
        *(float2*)(ob1 + c) = make_float2(__uint_as_float(f2tf(o[nt][2] * inv1)),
                                          __uint_as_float(f2tf(o[nt][3] * inv1)));
    }
}

// ---------------- launch ---------------------------------------------------
extern "C" void kernel_launch(void* const* d_in, const int* in_sizes, int n_in,
                              void* d_out, int out_size)
{
    const float* x     = (const float*)d_in[0];
    const float* ve    = (const float*)d_in[1];
    const float* cosT  = (const float*)d_in[2];
    const float* sinT  = (const float*)d_in[3];
    const float* Wq    = (const float*)d_in[4];
    const float* Wk    = (const float*)d_in[5];
    const float* Wv    = (const float*)d_in[6];
    const float* Wproj = (const float*)d_in[7];
    const float* Wg    = (const float*)d_in[8];
    float* out = (float*)d_out;

    float *q, *k, *v, *o, *xt, *wq, *wk, *wv, *wp;
    cudaGetSymbolAddress((void**)&q, g_q);
    cudaGetSymbolAddress((void**)&k, g_k);
    cudaGetSymbolAddress((void**)&v, g_v);
    cudaGetSymbolAddress((void**)&o, g_o);
    cudaGetSymbolAddress((void**)&xt, g_xt);
    cudaGetSymbolAddress((void**)&wq, g_wq);
    cudaGetSymbolAddress((void**)&wk, g_wk);
    cudaGetSymbolAddress((void**)&wv, g_wv);
    cudaGetSymbolAddress((void**)&wp, g_wp);

    static int attr_set = 0;
    if (!attr_set) {
        cudaFuncSetAttribute(attn_mma_kernel,
                             cudaFuncAttributeMaxDynamicSharedMemorySize,
                             SMEM_ATTN_BYTES);
        cudaFuncSetAttribute(tf32_gemm_pipe,
                             cudaFuncAttributeMaxDynamicSharedMemorySize,
                             GEMM_SMEM_BYTES);
        attr_set = 1;
    }

    // tf32 pre-round: x and weights
    const int nx4 = (M_ * C_) / 4;
    const int nw4 = (C_ * C_) / 4;
    round_tf32_kernel<<<nx4 / 256, 256>>>(x, xt, nx4);
    round_tf32_kernel<<<nw4 / 256, 256>>>(Wq, wq, nw4);
    round_tf32_kernel<<<nw4 / 256, 256>>>(Wk, wk, nw4);
    round_tf32_kernel<<<nw4 / 256, 256>>>(Wv, wv, nw4);
    round_tf32_kernel<<<nw4 / 256, 256>>>(Wproj, wp, nw4);

    dim3 gemm_grid(C_ / GBN, M_ / GBM);
    tf32_gemm_pipe<<<gemm_grid, 256, GEMM_SMEM_BYTES>>>(xt, wq, q, M_, C_, C_);
    tf32_gemm_pipe<<<gemm_grid, 256, GEMM_SMEM_BYTES>>>(xt, wk, k, M_, C_, C_);
    tf32_gemm_pipe<<<gemm_grid, 256, GEMM_SMEM_BYTES>>>(xt, wv, v, M_, C_, C_);

    gate_kernel<<<M_, 256>>>(x, ve, Wg, v);
    rope_rms_kernel<<<(M_ * H_) / 8, 256>>>(cosT, sinT, q, k);

    dim3 attn_grid(T_ / AQ, H_, B_);
    attn_mma_kernel<<<attn_grid, 256, SMEM_ATTN_BYTES>>>(q, k, v, o);

    tf32_gemm_pipe<<<gemm_grid, 256, GEMM_SMEM_BYTES>>>(o, wp, out, M_, C_, C_);
}